// round 15
// baseline (speedup 1.0000x reference)
#include <cuda_runtime.h>
#include <cuda_fp16.h>
#include <math.h>

#define FULL 0xffffffffu
constexpr int D = 64;
constexpr int MAXN = 50048;
constexpr int MAXE = 800000;
constexpr int MAXG = 128;
constexpr int SCAN_CHUNK = 16;
constexpr int SCAN_BLOCK = 256;
constexpr int SCAN_ELEMS = SCAN_BLOCK * SCAN_CHUNK;   // 4096 per block

// ---- scratch (no allocations allowed) ----
__device__ float g_x[MAXN * D];
__device__ float g_s[MAXN * D];
__device__ __half2 g_hs2a[MAXN * D];   // message buffers (double buffered)
__device__ __half2 g_hs2b[MAXN * D];
__device__ float g_aggx[MAXN * D];
__device__ float g_aggs[MAXN * D];
__device__ float g_dinv[MAXN];
__device__ float g_stats[2 * D];
__device__ float g_pooled[MAXG * D];
__device__ float g_M[2 * D * D];       // W2_l @ W1_{l+1}[0:64,:]
__device__ float g_Sla[MAXG * D];
__device__ float g_St[MAXG * D];
__device__ float g_C[D * D];
__device__ float g_cntf[MAXG];
__device__ int g_src[MAXE];
__device__ int g_dst[MAXE];
__device__ int g_csr[MAXE];
__device__ int g_batch[MAXN];
__device__ int g_degi[MAXN];
__device__ int g_rowstart[MAXN + 1];
__device__ int g_cursor[MAXN];
__device__ int g_blocksum[64];
__device__ int g_blockoff[64];
__device__ int g_is64;

// ---------------------------------------------------------------
__global__ void k_detect(const int* __restrict__ eraw, int totalInts) {
    __shared__ int anyNZ;
    if (threadIdx.x == 0) anyNZ = 0;
    __syncthreads();
    int limit = min(totalInts, 4096);
    for (int i = threadIdx.x * 2 + 1; i < limit; i += 512)
        if (eraw[i] != 0) anyNZ = 1;
    __syncthreads();
    if (threadIdx.x == 0) g_is64 = anyNZ ? 0 : 1;
}

__global__ void k_zero(float* pooled, int n, int G) {
    int i = blockIdx.x * blockDim.x + threadIdx.x;
    if (i < n) g_degi[i] = 0;
    if (i < 2 * D) g_stats[i] = 0.f;
    if (i < G * D) pooled[i] = 0.f;
    if (i < MAXG * D) { g_Sla[i] = 0.f; g_St[i] = 0.f; }
    if (i < D * D) g_C[i] = 0.f;
    if (i < MAXG) g_cntf[i] = 0.f;
}

// convert indices (+ degree histogram fused in)
__global__ void k_convert(const int* __restrict__ eraw, const int* __restrict__ braw,
                          int E, int n) {
    int i = blockIdx.x * blockDim.x + threadIdx.x;
    bool is64 = (g_is64 != 0);
    if (i < E) {
        int sv = is64 ? eraw[2 * i] : eraw[i];
        int dv = is64 ? eraw[2 * (E + i)] : eraw[E + i];
        if ((unsigned)sv >= (unsigned)n) sv = 0;
        if ((unsigned)dv >= (unsigned)n) dv = 0;
        g_src[i] = sv;
        g_dst[i] = dv;
        atomicAdd(&g_degi[dv], 1);
    }
    if (i < n) g_batch[i] = is64 ? braw[2 * i] : braw[i];
}

// ---------------------------------------------------------------
// 3-phase parallel exclusive scan over g_degi -> rowstart/cursor/dinv
__global__ void k_scan1(int n) {
    __shared__ int ts[SCAN_BLOCK];
    int t = threadIdx.x, b = blockIdx.x;
    int base = b * SCAN_ELEMS + t * SCAN_CHUNK;
    int sum = 0;
#pragma unroll
    for (int i = 0; i < SCAN_CHUNK; i++) {
        int idx = base + i;
        if (idx < n) sum += g_degi[idx];
    }
    ts[t] = sum;
    __syncthreads();
    for (int off = 128; off > 0; off >>= 1) {
        if (t < off) ts[t] += ts[t + off];
        __syncthreads();
    }
    if (t == 0) g_blocksum[b] = ts[0];
}

__global__ void k_scan2(int nb, int n) {
    __shared__ int sh[64];
    int t = threadIdx.x;   // 64 threads
    int v = (t < nb) ? g_blocksum[t] : 0;
    sh[t] = v;
    __syncthreads();
    for (int off = 1; off < 64; off <<= 1) {
        int vv = (t >= off) ? sh[t - off] : 0;
        __syncthreads();
        sh[t] += vv;
        __syncthreads();
    }
    if (t < nb) g_blockoff[t] = sh[t] - v;   // exclusive
    if (t == 63) g_rowstart[n] = sh[63];     // total
}

__global__ void k_scan3(int n) {
    __shared__ int ts[SCAN_BLOCK];
    int t = threadIdx.x, b = blockIdx.x;
    int base = b * SCAN_ELEMS + t * SCAN_CHUNK;
    int deg[SCAN_CHUNK];
    int sum = 0;
#pragma unroll
    for (int i = 0; i < SCAN_CHUNK; i++) {
        int idx = base + i;
        deg[i] = (idx < n) ? g_degi[idx] : 0;
        sum += deg[i];
    }
    ts[t] = sum;
    __syncthreads();
    for (int off = 1; off < SCAN_BLOCK; off <<= 1) {
        int v = (t >= off) ? ts[t - off] : 0;
        __syncthreads();
        ts[t] += v;
        __syncthreads();
    }
    int run = g_blockoff[b] + ts[t] - sum;   // exclusive start for this thread
#pragma unroll
    for (int i = 0; i < SCAN_CHUNK; i++) {
        int idx = base + i;
        if (idx < n) {
            g_rowstart[idx] = run;
            g_cursor[idx] = run;
            g_dinv[idx] = rsqrtf((float)deg[i] + 1.0f);
            run += deg[i];
        }
    }
}

__global__ void k_fill(int E) {
    int e = blockIdx.x * blockDim.x + threadIdx.x;
    if (e < E) {
        int pos = atomicAdd(&g_cursor[g_dst[e]], 1);
        g_csr[pos] = g_src[e];
    }
}

// ---------------------------------------------------------------
// M[l] = W2_l @ W1_{l+1}[0:64,:]
__global__ void k_precompute(const float* __restrict__ W1, const float* __restrict__ W2) {
    int b = blockIdx.x;
    int l = b >> 6, k = b & 63;
    int c = threadIdx.x;
    const float* W2l = W2 + l * 4096;
    const float* W1a = W1 + (l + 1) * 8192;
    float acc = 0.f;
#pragma unroll 16
    for (int j = 0; j < 64; j++) acc = fmaf(W2l[k * 64 + j], W1a[j * 64 + c], acc);
    g_M[l * 4096 + k * 64 + c] = acc;
}

// ---------------------------------------------------------------
// Layer-0 GEMM: hw = x@W1a + s@W1b ; sws = dinv*(s@Wg).
// Lane computes adjacent cols (2l, 2l+1); packs half2; interleaved store.
__global__ void k1_gemm(const float* __restrict__ xin, const float* __restrict__ sin,
                        const float* __restrict__ W1, const float* __restrict__ Wg,
                        __half2* __restrict__ hsout, int n) {
    __shared__ float W1s[128 * 64];
    __shared__ float Wgs[64 * 64];
    int tid = threadIdx.x;
    for (int i = tid; i < 128 * 64; i += 256) W1s[i] = W1[i];
    for (int i = tid; i < 64 * 64; i += 256) Wgs[i] = Wg[i];
    __syncthreads();
    int lane = tid & 31;
    int warp = blockIdx.x * 8 + (tid >> 5);
    int r0 = warp * 4;
    if (r0 >= n) return;

    const float2* W1p = (const float2*)W1s;
    const float2* Wgp = (const float2*)Wgs;

    float xa[4], xb[4], sa[4], sb[4];
#pragma unroll
    for (int r = 0; r < 4; r++) {
        int row = min(r0 + r, n - 1);
        xa[r] = xin[row * 64 + lane];  xb[r] = xin[row * 64 + 32 + lane];
        sa[r] = sin[row * 64 + lane];  sb[r] = sin[row * 64 + 32 + lane];
    }
    float h0[4] = {0,0,0,0}, h1[4] = {0,0,0,0}, w0[4] = {0,0,0,0}, w1[4] = {0,0,0,0};
#pragma unroll 8
    for (int k = 0; k < 32; k++) {
        float2 wa = W1p[k * 32 + lane];
        float2 wb = W1p[(64 + k) * 32 + lane];
        float2 wg = Wgp[k * 32 + lane];
#pragma unroll
        for (int r = 0; r < 4; r++) {
            float xv = __shfl_sync(FULL, xa[r], k);
            float sv = __shfl_sync(FULL, sa[r], k);
            h0[r] += xv * wa.x;  h0[r] += sv * wb.x;
            h1[r] += xv * wa.y;  h1[r] += sv * wb.y;
            w0[r] += sv * wg.x;  w1[r] += sv * wg.y;
        }
    }
#pragma unroll 8
    for (int k = 0; k < 32; k++) {
        int kk = k + 32;
        float2 wa = W1p[kk * 32 + lane];
        float2 wb = W1p[(64 + kk) * 32 + lane];
        float2 wg = Wgp[kk * 32 + lane];
#pragma unroll
        for (int r = 0; r < 4; r++) {
            float xv = __shfl_sync(FULL, xb[r], k);
            float sv = __shfl_sync(FULL, sb[r], k);
            h0[r] += xv * wa.x;  h0[r] += sv * wb.x;
            h1[r] += xv * wa.y;  h1[r] += sv * wb.y;
            w0[r] += sv * wg.x;  w1[r] += sv * wg.y;
        }
    }
#pragma unroll
    for (int r = 0; r < 4; r++) {
        int row = r0 + r;
        if (row >= n) break;
        float dvr = g_dinv[row];
        hsout[row * 64 + lane]      = __floats2half2_rn(h0[r], h1[r]);
        hsout[row * 64 + 32 + lane] = __floats2half2_rn(dvr * w0[r], dvr * w1[r]);
    }
}

// ---------------------------------------------------------------
// FUSED gather + layer GEMM (layers 1,2). Warp handles 4 consecutive nodes:
// gathers messages (fp32 acc), applies leaky/tanh in-register, runs the
// 4-row shfl GEMM (lane-pair broadcast), writes half2 messages to hsout.
__global__ void k_gg(const __half2* __restrict__ hsin, __half2* __restrict__ hsout,
                     const float* __restrict__ M, const float* __restrict__ W1b,
                     const float* __restrict__ Wg, const float* __restrict__ bgp, int n) {
    __shared__ float Ms[64 * 64];
    __shared__ float Bs[64 * 64];
    __shared__ float Gs[64 * 64];
    int tid = threadIdx.x;
    for (int i = tid; i < 64 * 64; i += 256) { Ms[i] = M[i]; Bs[i] = W1b[i]; Gs[i] = Wg[i]; }
    __syncthreads();
    int lane = tid & 31;
    int warp = blockIdx.x * 8 + (tid >> 5);
    int r0 = warp * 4;
    if (r0 >= n) return;

    // --- gather phase: 4 rows, lane holds cols (2l,2l+1) of both streams ---
    float aa0[4], aa1[4], ta0[4], ta1[4];
    float b0v = bgp[2 * lane], b1v = bgp[2 * lane + 1];
#pragma unroll
    for (int r = 0; r < 4; r++) {
        int row = min(r0 + r, n - 1);
        float2 h = __half22float2(hsin[row * 64 + lane]);
        float2 w = __half22float2(hsin[row * 64 + 32 + lane]);
        float ax0 = h.x, ax1 = h.y, as0 = w.x, as1 = w.y;
        int beg = g_rowstart[row], end = g_rowstart[row + 1];
        int j = beg;
        for (; j + 4 <= end; j += 4) {
            int s0 = g_csr[j], s1 = g_csr[j + 1], s2 = g_csr[j + 2], s3 = g_csr[j + 3];
            float2 f0 = __half22float2(hsin[s0 * 64 + lane]);
            float2 g0 = __half22float2(hsin[s0 * 64 + 32 + lane]);
            float2 f1 = __half22float2(hsin[s1 * 64 + lane]);
            float2 g1 = __half22float2(hsin[s1 * 64 + 32 + lane]);
            float2 f2 = __half22float2(hsin[s2 * 64 + lane]);
            float2 g2 = __half22float2(hsin[s2 * 64 + 32 + lane]);
            float2 f3 = __half22float2(hsin[s3 * 64 + lane]);
            float2 g3 = __half22float2(hsin[s3 * 64 + 32 + lane]);
            ax0 += f0.x + f1.x + f2.x + f3.x;
            ax1 += f0.y + f1.y + f2.y + f3.y;
            as0 += g0.x + g1.x + g2.x + g3.x;
            as1 += g0.y + g1.y + g2.y + g3.y;
        }
        for (; j < end; j++) {
            int sid = g_csr[j];
            float2 f = __half22float2(hsin[sid * 64 + lane]);
            float2 g2v = __half22float2(hsin[sid * 64 + 32 + lane]);
            ax0 += f.x; ax1 += f.y;
            as0 += g2v.x; as1 += g2v.y;
        }
        float dv = g_dinv[row];
        aa0[r] = ax0 > 0.f ? ax0 : 0.01f * ax0;
        aa1[r] = ax1 > 0.f ? ax1 : 0.01f * ax1;
        ta0[r] = tanhf(dv * as0 + b0v);
        ta1[r] = tanhf(dv * as1 + b1v);
    }

    // --- GEMM phase: per kk broadcast lane kk's col pair (k=2kk, 2kk+1) ---
    const float2* Mp = (const float2*)Ms;
    const float2* Bp = (const float2*)Bs;
    const float2* Gp = (const float2*)Gs;
    float h0[4] = {0,0,0,0}, h1[4] = {0,0,0,0}, w0[4] = {0,0,0,0}, w1[4] = {0,0,0,0};
#pragma unroll 4
    for (int kk = 0; kk < 32; kk++) {
        float2 wae = Mp[(2 * kk) * 32 + lane];
        float2 wao = Mp[(2 * kk + 1) * 32 + lane];
        float2 wbe = Bp[(2 * kk) * 32 + lane];
        float2 wbo = Bp[(2 * kk + 1) * 32 + lane];
        float2 wge = Gp[(2 * kk) * 32 + lane];
        float2 wgo = Gp[(2 * kk + 1) * 32 + lane];
#pragma unroll
        for (int r = 0; r < 4; r++) {
            float ae = __shfl_sync(FULL, aa0[r], kk);
            float ao = __shfl_sync(FULL, aa1[r], kk);
            float te = __shfl_sync(FULL, ta0[r], kk);
            float to = __shfl_sync(FULL, ta1[r], kk);
            h0[r] += ae * wae.x; h0[r] += ao * wao.x; h0[r] += te * wbe.x; h0[r] += to * wbo.x;
            h1[r] += ae * wae.y; h1[r] += ao * wao.y; h1[r] += te * wbe.y; h1[r] += to * wbo.y;
            w0[r] += te * wge.x; w0[r] += to * wgo.x;
            w1[r] += te * wge.y; w1[r] += to * wgo.y;
        }
    }
#pragma unroll
    for (int r = 0; r < 4; r++) {
        int row = r0 + r;
        if (row >= n) break;
        float dvr = g_dinv[row];
        hsout[row * 64 + lane]      = __floats2half2_rn(h0[r], h1[r]);
        hsout[row * 64 + 32 + lane] = __floats2half2_rn(dvr * w0[r], dvr * w1[r]);
    }
}

// ---------------------------------------------------------------
// Final CSR gather (layer 3): writes fp32 aggx/aggs for the tail.
__global__ void k_gather(const __half2* __restrict__ hsin, int n) {
    int di = blockIdx.x * 8 + (threadIdx.x >> 5);
    if (di >= n) return;
    int lane = threadIdx.x & 31;
    float2 hx = __half22float2(hsin[di * 64 + lane]);
    float2 hw = __half22float2(hsin[di * 64 + 32 + lane]);
    float ax0 = hx.x, ax1 = hx.y;
    float as0 = hw.x, as1 = hw.y;
    int beg = g_rowstart[di], end = g_rowstart[di + 1];
    int j = beg;
    for (; j + 4 <= end; j += 4) {
        int s0 = g_csr[j], s1 = g_csr[j + 1], s2 = g_csr[j + 2], s3 = g_csr[j + 3];
        float2 f0 = __half22float2(hsin[s0 * 64 + lane]);
        float2 g0 = __half22float2(hsin[s0 * 64 + 32 + lane]);
        float2 f1 = __half22float2(hsin[s1 * 64 + lane]);
        float2 g1 = __half22float2(hsin[s1 * 64 + 32 + lane]);
        float2 f2 = __half22float2(hsin[s2 * 64 + lane]);
        float2 g2 = __half22float2(hsin[s2 * 64 + 32 + lane]);
        float2 f3 = __half22float2(hsin[s3 * 64 + lane]);
        float2 g3 = __half22float2(hsin[s3 * 64 + 32 + lane]);
        ax0 += f0.x + f1.x + f2.x + f3.x;
        ax1 += f0.y + f1.y + f2.y + f3.y;
        as0 += g0.x + g1.x + g2.x + g3.x;
        as1 += g0.y + g1.y + g2.y + g3.y;
    }
    for (; j < end; j++) {
        int sid = g_csr[j];
        float2 f = __half22float2(hsin[sid * 64 + lane]);
        float2 g2v = __half22float2(hsin[sid * 64 + 32 + lane]);
        ax0 += f.x; ax1 += f.y;
        as0 += g2v.x; as1 += g2v.y;
    }
    float dv = g_dinv[di];
    // store cols (2l,2l+1) — pair layout, consumed by tail/fallback below
    ((float2*)g_aggx)[di * 32 + lane] = make_float2(ax0, ax1);
    ((float2*)g_aggs)[di * 32 + lane] = make_float2(dv * as0, dv * as1);
}

// ---------------------------------------------------------------
// FAST TAIL (pooled-only): one pass over aggx/aggs (pair layout = plain
// column order: index di*64 + 2*lane (+1) == linear col index; unchanged).
__global__ void k_tail(const float* __restrict__ bg, int n, int G) {
    __shared__ float la_s[128 * 64];   // 32KB
    int tid = threadIdx.x;
    int c = tid & 63, q = tid >> 6;
    int r0 = blockIdx.x * 128;
    float bgc = bg[c];
    float accL = 0.f, accT = 0.f, cntRun = 0.f;
    int curg = -1;
    for (int rr = q; rr < 128; rr += 4) {
        int r = r0 + rr;
        if (r < n) {
            float v = g_aggx[r * 64 + c];
            float la = v > 0.f ? v : 0.01f * v;
            la_s[rr * 64 + c] = la;
            float tv = tanhf(g_aggs[r * 64 + c] + bgc);
            int g = g_batch[r];
            if ((unsigned)g >= (unsigned)G) g = 0;
            if (g != curg) {
                if (curg >= 0) {
                    atomicAdd(&g_Sla[curg * 64 + c], accL);
                    atomicAdd(&g_St[curg * 64 + c], accT);
                    if (c == 0) atomicAdd(&g_cntf[curg], cntRun);
                }
                curg = g; accL = 0.f; accT = 0.f; cntRun = 0.f;
            }
            accL += la; accT += tv; cntRun += 1.f;
        } else {
            la_s[rr * 64 + c] = 0.f;
        }
    }
    if (curg >= 0) {
        atomicAdd(&g_Sla[curg * 64 + c], accL);
        atomicAdd(&g_St[curg * 64 + c], accT);
        if (c == 0) atomicAdd(&g_cntf[curg], cntRun);
    }
    __syncthreads();
    // covariance: thread computes a 4x4 tile of C
    int a0 = (tid >> 4) * 4, b0 = (tid & 15) * 4;
    float C00=0,C01=0,C02=0,C03=0, C10=0,C11=0,C12=0,C13=0;
    float C20=0,C21=0,C22=0,C23=0, C30=0,C31=0,C32=0,C33=0;
    for (int r = 0; r < 128; r++) {
        float4 va = *(const float4*)&la_s[r * 64 + a0];
        float4 vb = *(const float4*)&la_s[r * 64 + b0];
        C00 += va.x*vb.x; C01 += va.x*vb.y; C02 += va.x*vb.z; C03 += va.x*vb.w;
        C10 += va.y*vb.x; C11 += va.y*vb.y; C12 += va.y*vb.z; C13 += va.y*vb.w;
        C20 += va.z*vb.x; C21 += va.z*vb.y; C22 += va.z*vb.z; C23 += va.z*vb.w;
        C30 += va.w*vb.x; C31 += va.w*vb.y; C32 += va.w*vb.z; C33 += va.w*vb.w;
    }
    atomicAdd(&g_C[(a0+0)*64+b0+0], C00); atomicAdd(&g_C[(a0+0)*64+b0+1], C01);
    atomicAdd(&g_C[(a0+0)*64+b0+2], C02); atomicAdd(&g_C[(a0+0)*64+b0+3], C03);
    atomicAdd(&g_C[(a0+1)*64+b0+0], C10); atomicAdd(&g_C[(a0+1)*64+b0+1], C11);
    atomicAdd(&g_C[(a0+1)*64+b0+2], C12); atomicAdd(&g_C[(a0+1)*64+b0+3], C13);
    atomicAdd(&g_C[(a0+2)*64+b0+0], C20); atomicAdd(&g_C[(a0+2)*64+b0+1], C21);
    atomicAdd(&g_C[(a0+2)*64+b0+2], C22); atomicAdd(&g_C[(a0+2)*64+b0+3], C23);
    atomicAdd(&g_C[(a0+3)*64+b0+0], C30); atomicAdd(&g_C[(a0+3)*64+b0+1], C31);
    atomicAdd(&g_C[(a0+3)*64+b0+2], C32); atomicAdd(&g_C[(a0+3)*64+b0+3], C33);
}

// BN stats from covariance
__global__ void k_bn2(const float* __restrict__ W2, int n, int G) {
    __shared__ float Cs[4096];
    __shared__ float W2s[4096];
    __shared__ float qpart[256];
    __shared__ float Tla[64];
    int tid = threadIdx.x;
    for (int i = tid; i < 4096; i += 256) { Cs[i] = g_C[i]; W2s[i] = W2[i]; }
    __syncthreads();
    int c = tid & 63, p = tid >> 6;
    float part = 0.f;
    for (int r = p; r < 64; r += 4) {
        float inner = 0.f;
#pragma unroll 16
        for (int k = 0; k < 64; k++) inner = fmaf(Cs[r * 64 + k], W2s[k * 64 + c], inner);
        part = fmaf(W2s[r * 64 + c], inner, part);
    }
    qpart[tid] = part;
    if (tid < 64) {
        float t = 0.f;
        for (int g = 0; g < G; g++) t += g_Sla[g * 64 + tid];
        Tla[tid] = t;
    }
    __syncthreads();
    if (tid < 64) {
        float quad = qpart[tid] + qpart[64 + tid] + qpart[128 + tid] + qpart[192 + tid];
        float mean = 0.f;
#pragma unroll 16
        for (int k = 0; k < 64; k++) mean = fmaf(Tla[k], W2s[k * 64 + tid], mean);
        mean /= (float)n;
        float var = quad / (float)n - mean * mean;
        g_stats[tid] = mean;
        g_stats[64 + tid] = rsqrtf(var + 1e-4f);
    }
}

__global__ void k_pool(const float* __restrict__ W2, const float* __restrict__ gamma,
                       const float* __restrict__ beta, const float* __restrict__ Wh,
                       const float* __restrict__ bh, float* __restrict__ pooled) {
    __shared__ float Sl[64], Stm[64], xls[64];
    int g = blockIdx.x;
    int c = threadIdx.x;
    Sl[c] = g_Sla[g * 64 + c];
    Stm[c] = g_St[g * 64 + c];
    float cnt = g_cntf[g];
    __syncthreads();
    float sx3 = 0.f;
#pragma unroll 16
    for (int k = 0; k < 64; k++) sx3 = fmaf(Sl[k], W2[k * 64 + c], sx3);
    float m = g_stats[c], iv = g_stats[64 + c];
    xls[c] = gamma[c] * iv * (sx3 - cnt * m) + cnt * beta[c];
    __syncthreads();
    float o = cnt * bh[c];
#pragma unroll 16
    for (int k = 0; k < 64; k++) o = fmaf(xls[k], Wh[k * 64 + c], o);
#pragma unroll 16
    for (int k = 0; k < 64; k++) o = fmaf(Stm[k], Wh[(64 + k) * 64 + c], o);
    pooled[g * 64 + c] = o;
}

// ---------------------------------------------------------------
// FALLBACK PATH (x_local output required)
__global__ void k3_mlp(const float* __restrict__ W2, const float* __restrict__ bg, int n) {
    __shared__ float Ws[64 * 64];
    __shared__ float shst[128];
    int tid = threadIdx.x;
    for (int i = tid; i < 64 * 64; i += 256) Ws[i] = W2[i];
    if (tid < 128) shst[tid] = 0.f;
    __syncthreads();
    int lane = tid & 31;
    int warp = blockIdx.x * 8 + (tid >> 5);
    int r0 = warp * 4;
    bool active = (r0 < n);
    float sum0 = 0.f, sum1 = 0.f, sq0 = 0.f, sq1 = 0.f;
    if (active) {
        float a0[4], a1[4];
#pragma unroll
        for (int r = 0; r < 4; r++) {
            int row = min(r0 + r, n - 1);
            float v0 = g_aggx[row * 64 + lane], v1 = g_aggx[row * 64 + 32 + lane];
            a0[r] = v0 > 0.f ? v0 : 0.01f * v0;
            a1[r] = v1 > 0.f ? v1 : 0.01f * v1;
        }
        float o0[4] = {0,0,0,0}, o1[4] = {0,0,0,0};
#pragma unroll 8
        for (int k = 0; k < 32; k++) {
            float w = Ws[k * 64 + lane], w2 = Ws[k * 64 + 32 + lane];
#pragma unroll
            for (int r = 0; r < 4; r++) {
                float xv = __shfl_sync(FULL, a0[r], k);
                o0[r] += xv * w; o1[r] += xv * w2;
            }
        }
#pragma unroll 8
        for (int k = 0; k < 32; k++) {
            int kk = k + 32;
            float w = Ws[kk * 64 + lane], w2 = Ws[kk * 64 + 32 + lane];
#pragma unroll
            for (int r = 0; r < 4; r++) {
                float xv = __shfl_sync(FULL, a1[r], k);
                o0[r] += xv * w; o1[r] += xv * w2;
            }
        }
        float b0 = bg[lane], b1 = bg[32 + lane];
#pragma unroll
        for (int r = 0; r < 4; r++) {
            int row = r0 + r;
            if (row >= n) break;
            g_x[row * 64 + lane] = o0[r]; g_x[row * 64 + 32 + lane] = o1[r];
            g_s[row * 64 + lane]      = tanhf(g_aggs[row * 64 + lane] + b0);
            g_s[row * 64 + 32 + lane] = tanhf(g_aggs[row * 64 + 32 + lane] + b1);
            sum0 += o0[r]; sq0 += o0[r] * o0[r];
            sum1 += o1[r]; sq1 += o1[r] * o1[r];
        }
    }
    atomicAdd(&shst[lane], sum0);
    atomicAdd(&shst[32 + lane], sum1);
    atomicAdd(&shst[64 + lane], sq0);
    atomicAdd(&shst[96 + lane], sq1);
    __syncthreads();
    if (tid < 128) atomicAdd(&g_stats[tid], shst[tid]);
}

__global__ void k_bn(int n) {
    int c = threadIdx.x;
    float mean = g_stats[c] / (float)n;
    float var = g_stats[64 + c] / (float)n - mean * mean;
    g_stats[c] = mean;
    g_stats[64 + c] = rsqrtf(var + 1e-4f);
}

__global__ void k_final(const float* __restrict__ gamma, const float* __restrict__ beta,
                        const float* __restrict__ Wh, const float* __restrict__ bh,
                        float* __restrict__ pooled, float* __restrict__ xl_out,
                        int n, int G) {
    __shared__ float Ws[128 * 64];
    int tid = threadIdx.x;
    for (int i = tid; i < 128 * 64; i += 256) Ws[i] = Wh[i];
    __syncthreads();
    int lane = tid & 31;
    int warp = blockIdx.x * 8 + (tid >> 5);
    int r0 = warp * 4;
    if (r0 >= n) return;
    float m0 = g_stats[lane],      m1 = g_stats[32 + lane];
    float i0 = g_stats[64 + lane], i1 = g_stats[96 + lane];
    float ga0 = gamma[lane], ga1 = gamma[32 + lane];
    float be0 = beta[lane],  be1 = beta[32 + lane];
    float xl0[4], xl1[4], sv0[4], sv1[4];
    int bidx[4];
#pragma unroll
    for (int r = 0; r < 4; r++) {
        int row = min(r0 + r, n - 1);
        xl0[r] = ga0 * (g_x[row * 64 + lane] - m0) * i0 + be0;
        xl1[r] = ga1 * (g_x[row * 64 + 32 + lane] - m1) * i1 + be1;
        sv0[r] = g_s[row * 64 + lane];
        sv1[r] = g_s[row * 64 + 32 + lane];
        int b = g_batch[row];
        bidx[r] = ((unsigned)b < (unsigned)G) ? b : 0;
    }
    float bh0 = bh[lane], bh1 = bh[32 + lane];
    float o0[4], o1[4];
#pragma unroll
    for (int r = 0; r < 4; r++) { o0[r] = bh0; o1[r] = bh1; }
#pragma unroll 8
    for (int k = 0; k < 32; k++) {
        float w = Ws[k * 64 + lane], w2 = Ws[k * 64 + 32 + lane];
#pragma unroll
        for (int r = 0; r < 4; r++) { float v = __shfl_sync(FULL, xl0[r], k); o0[r] += v * w; o1[r] += v * w2; }
    }
#pragma unroll 8
    for (int k = 0; k < 32; k++) {
        int kk = 32 + k;
        float w = Ws[kk * 64 + lane], w2 = Ws[kk * 64 + 32 + lane];
#pragma unroll
        for (int r = 0; r < 4; r++) { float v = __shfl_sync(FULL, xl1[r], k); o0[r] += v * w; o1[r] += v * w2; }
    }
#pragma unroll 8
    for (int k = 0; k < 32; k++) {
        int kk = 64 + k;
        float w = Ws[kk * 64 + lane], w2 = Ws[kk * 64 + 32 + lane];
#pragma unroll
        for (int r = 0; r < 4; r++) { float v = __shfl_sync(FULL, sv0[r], k); o0[r] += v * w; o1[r] += v * w2; }
    }
#pragma unroll 8
    for (int k = 0; k < 32; k++) {
        int kk = 96 + k;
        float w = Ws[kk * 64 + lane], w2 = Ws[kk * 64 + 32 + lane];
#pragma unroll
        for (int r = 0; r < 4; r++) { float v = __shfl_sync(FULL, sv1[r], k); o0[r] += v * w; o1[r] += v * w2; }
    }
    if (xl_out) {
#pragma unroll
        for (int r = 0; r < 4; r++) {
            int row = r0 + r;
            if (row >= n) break;
            xl_out[row * 64 + lane] = xl0[r];
            xl_out[row * 64 + 32 + lane] = xl1[r];
        }
    }
    int nvalid = min(n - r0, 4);
    for (int r = 0; r < nvalid; r++) {
        atomicAdd(&pooled[bidx[r] * 64 + lane], o0[r]);
        atomicAdd(&pooled[bidx[r] * 64 + 32 + lane], o1[r]);
    }
}

// ---------------------------------------------------------------
extern "C" void kernel_launch(void* const* d_in, const int* in_sizes, int n_in,
                              void* d_out, int out_size) {
    int ix, is_, iW1, iW2, iGa, iBe, iWg, iBg, iWh, iBh, iEi, iBa;
    if (n_in >= 2 && in_sizes[0] == in_sizes[1]) {
        ix = 0; is_ = 1; iW1 = 2; iW2 = 3; iGa = 4; iBe = 5;
        iWg = 6; iBg = 7; iWh = 8; iBh = 9; iEi = 10; iBa = 11;
    } else {
        iW1 = 0; iW2 = 1; iWg = 2; iWh = 3; iBa = 4; iBe = 5;
        iBg = 6; iBh = 7; iEi = 8; iGa = 9; is_ = 10; ix = 11;
    }

    const float* x     = (const float*)d_in[ix];
    const float* s     = (const float*)d_in[is_];
    const float* W1    = (const float*)d_in[iW1];
    const float* W2    = (const float*)d_in[iW2];
    const float* gamma = (const float*)d_in[iGa];
    const float* beta  = (const float*)d_in[iBe];
    const float* Wg    = (const float*)d_in[iWg];
    const float* bg    = (const float*)d_in[iBg];
    const float* Wh    = (const float*)d_in[iWh];
    const float* bh    = (const float*)d_in[iBh];
    const int* eraw    = (const int*)d_in[iEi];
    const int* braw    = (const int*)d_in[iBa];
    float* out = (float*)d_out;

    int n = in_sizes[ix] / 64;
    int E = in_sizes[iEi] / 2;
    if (n > MAXN) n = MAXN;
    if (E > MAXE) E = MAXE;

    // ---- output layout resolution ----
    float* pooledPtr;
    float* xlocalPtr;
    int G;
    float* gpool;
    cudaGetSymbolAddress((void**)&gpool, g_pooled);
    if (out_size > n * 64) {
        G = out_size / 64 - n;
        pooledPtr = out;
        xlocalPtr = out + (long)G * 64;
    } else if (out_size == n * 64) {
        G = 64;
        pooledPtr = gpool;
        xlocalPtr = out;
    } else {
        G = out_size / 64;
        pooledPtr = out;
        xlocalPtr = nullptr;
    }
    if (G > MAXG) G = MAXG;
    if (G < 1) G = 1;

    int gemmBlocks = (((n + 3) / 4) + 7) / 8;
    int nodeBlocks = (n + 7) / 8;
    int cvtBlocks = ((E > n ? E : n) + 255) / 256;
    int scanBlocks = (n + SCAN_ELEMS - 1) / SCAN_ELEMS;
    float* d_M;
    cudaGetSymbolAddress((void**)&d_M, g_M);
    __half2 *hsA, *hsB;
    cudaGetSymbolAddress((void**)&hsA, g_hs2a);
    cudaGetSymbolAddress((void**)&hsB, g_hs2b);

    // setup
    k_detect<<<1, 256>>>(eraw, 2 * E);
    k_zero<<<(n + 255) / 256, 256>>>(pooledPtr, n, G);
    k_convert<<<cvtBlocks, 256>>>(eraw, braw, E, n);
    k_scan1<<<scanBlocks, SCAN_BLOCK>>>(n);
    k_scan2<<<1, 64>>>(scanBlocks, n);
    k_scan3<<<scanBlocks, SCAN_BLOCK>>>(n);
    k_fill<<<(E + 255) / 256, 256>>>(E);
    k_precompute<<<128, 64>>>(W1, W2);

    // layer 0 transform -> A
    k1_gemm<<<gemmBlocks, 256>>>(x, s, W1, Wg, hsA, n);
    // fused gather+GEMM layer 1: A -> B
    k_gg<<<gemmBlocks, 256>>>(hsA, hsB, d_M, W1 + 1 * 128 * 64 + 64 * 64,
                              Wg + 1 * 64 * 64, bg, n);
    // fused gather+GEMM layer 2: B -> A
    k_gg<<<gemmBlocks, 256>>>(hsB, hsA, d_M + 4096, W1 + 2 * 128 * 64 + 64 * 64,
                              Wg + 2 * 64 * 64, bg + 64, n);
    // final gather (layer 3): A -> aggx/aggs
    k_gather<<<nodeBlocks, 256>>>(hsA, n);

    if (xlocalPtr == nullptr) {
        // FAST TAIL: pooled-only, x3/s never materialized
        k_tail<<<(n + 127) / 128, 256>>>(bg + 2 * 64, n, G);
        k_bn2<<<1, 256>>>(W2 + 2 * 64 * 64, n, G);
        k_pool<<<G, 64>>>(W2 + 2 * 64 * 64, gamma + 2 * 64, beta + 2 * 64, Wh, bh, pooledPtr);
    } else {
        // fallback: x_local required (aggx/aggs are in pair layout == plain order)
        k3_mlp<<<gemmBlocks, 256>>>(W2 + 2 * 64 * 64, bg + 2 * 64, n);
        k_bn<<<1, 64>>>(n);
        k_final<<<gemmBlocks, 256>>>(gamma + 2 * 64, beta + 2 * 64, Wh, bh,
                                     pooledPtr, xlocalPtr, n, G);
    }
}